// round 1
// baseline (speedup 1.0000x reference)
#include <cuda_runtime.h>
#include <math.h>

#define THREADS 192
#define MAXD 104   // max padded layer width

// ---------------- 3x3 helpers (register matrices, fully unrolled) ----------
__device__ __forceinline__ void mm3(const float* a, const float* b, float* c) {
#pragma unroll
    for (int r = 0; r < 3; ++r)
#pragma unroll
        for (int k = 0; k < 3; ++k)
            c[r * 3 + k] = a[r * 3 + 0] * b[0 * 3 + k]
                         + a[r * 3 + 1] * b[1 * 3 + k]
                         + a[r * 3 + 2] * b[2 * 3 + k];
}
__device__ __forceinline__ float tr3(const float* a) { return a[0] + a[4] + a[8]; }
__device__ __forceinline__ float trAB(const float* a, const float* b) {
    float t = 0.f;
#pragma unroll
    for (int i = 0; i < 3; ++i)
#pragma unroll
        for (int k = 0; k < 3; ++k)
            t += a[i * 3 + k] * b[k * 3 + i];
    return t;
}
__device__ __forceinline__ void axpy9(float* acc, float g, const float* m) {
#pragma unroll
    for (int k = 0; k < 9; ++k) acc[k] += g * m[k];
}
__device__ __forceinline__ void axmy9(float* acc, float g, const float* m, const float* n) {
#pragma unroll
    for (int k = 0; k < 9; ++k) acc[k] += g * (m[k] - n[k]);
}

// ---------------- one MLP layer: stage weights -> padded GEMV tile ---------
template <int KPAD, int NPAD, int KTRUE, int NTRUE, bool RELU>
__device__ __forceinline__ void mlp_layer(
    const float* __restrict__ Wg, const float* __restrict__ Bg,
    float* __restrict__ wbuf, float* __restrict__ bbuf,
    const float* __restrict__ xin, float* __restrict__ xout, int tid)
{
    __syncthreads();  // previous layer done reading wbuf
    for (int idx = tid; idx < KPAD * NPAD; idx += THREADS) {
        int i = idx / NPAD;
        int j = idx - i * NPAD;
        wbuf[idx] = (i < KTRUE && j < NTRUE) ? Wg[i * NTRUE + j] : 0.f;
    }
    for (int j = tid; j < NPAD; j += THREADS)
        bbuf[j] = (j < NTRUE) ? Bg[j] : 0.f;
    __syncthreads();

#pragma unroll 1
    for (int jt = 0; jt < NPAD; jt += 8) {
        float a0 = bbuf[jt + 0], a1 = bbuf[jt + 1], a2 = bbuf[jt + 2], a3 = bbuf[jt + 3];
        float a4 = bbuf[jt + 4], a5 = bbuf[jt + 5], a6 = bbuf[jt + 6], a7 = bbuf[jt + 7];
#pragma unroll 4
        for (int i = 0; i < KPAD; ++i) {
            float xi = xin[i * THREADS + tid];
            const float4* wr = reinterpret_cast<const float4*>(wbuf + i * NPAD + jt);
            float4 wA = wr[0];
            float4 wB = wr[1];
            a0 += xi * wA.x; a1 += xi * wA.y; a2 += xi * wA.z; a3 += xi * wA.w;
            a4 += xi * wB.x; a5 += xi * wB.y; a6 += xi * wB.z; a7 += xi * wB.w;
        }
        if (RELU) {
            a0 = fmaxf(a0, 0.1f * a0); a1 = fmaxf(a1, 0.1f * a1);
            a2 = fmaxf(a2, 0.1f * a2); a3 = fmaxf(a3, 0.1f * a3);
            a4 = fmaxf(a4, 0.1f * a4); a5 = fmaxf(a5, 0.1f * a5);
            a6 = fmaxf(a6, 0.1f * a6); a7 = fmaxf(a7, 0.1f * a7);
        }
        xout[(jt + 0) * THREADS + tid] = a0;
        xout[(jt + 1) * THREADS + tid] = a1;
        xout[(jt + 2) * THREADS + tid] = a2;
        xout[(jt + 3) * THREADS + tid] = a3;
        xout[(jt + 4) * THREADS + tid] = a4;
        xout[(jt + 5) * THREADS + tid] = a5;
        xout[(jt + 6) * THREADS + tid] = a6;
        xout[(jt + 7) * THREADS + tid] = a7;
    }
}

// SMEM floats: wbuf 104*104 + bbuf 104 + act 2*104*192
#define SMEM_FLOATS (MAXD * MAXD + MAXD + 2 * MAXD * THREADS)

__global__ void __launch_bounds__(THREADS, 1) tbnn_kernel(
    const float* __restrict__ Sg, const float* __restrict__ Wg,
    const float* __restrict__ W0, const float* __restrict__ B0,
    const float* __restrict__ W1, const float* __restrict__ B1,
    const float* __restrict__ W2, const float* __restrict__ B2,
    const float* __restrict__ W3, const float* __restrict__ B3,
    const float* __restrict__ W4, const float* __restrict__ B4,
    const float* __restrict__ W5, const float* __restrict__ B5,
    float* __restrict__ out, int Btot)
{
    extern __shared__ float smem[];
    float* wbuf = smem;                    // MAXD*MAXD
    float* bbuf = wbuf + MAXD * MAXD;      // MAXD
    float* act0 = bbuf + MAXD;             // MAXD*THREADS
    float* act1 = act0 + MAXD * THREADS;   // MAXD*THREADS

    const int tid = threadIdx.x;
    const long b = (long)blockIdx.x * THREADS + tid;
    const long bb = (b < Btot) ? b : (long)Btot - 1;

    // ---- load s, w (kept in registers through the whole kernel) ----
    float s[9], w[9];
#pragma unroll
    for (int k = 0; k < 9; ++k) {
        s[k] = Sg[bb * 9 + k];
        w[k] = Wg[bb * 9 + k];
    }

    // ---- invariants ----
    {
        float s2[9], w2[9];
        mm3(s, s, s2);
        mm3(w, w, w2);
        float inv0 = tr3(s2);
        float inv1 = tr3(w2);
        float inv2 = trAB(s2, s);
        float inv3 = trAB(w2, s);
        float inv4 = trAB(w2, s2);
        act0[0 * THREADS + tid] = inv0;
        act0[1 * THREADS + tid] = inv1;
        act0[2 * THREADS + tid] = inv2;
        act0[3 * THREADS + tid] = inv3;
        act0[4 * THREADS + tid] = inv4;
        act0[5 * THREADS + tid] = 0.f;
        act0[6 * THREADS + tid] = 0.f;
        act0[7 * THREADS + tid] = 0.f;
    }

    // ---- MLP: 5 -> 50 -> 100 -> 100 -> 100 -> 50 -> 10 (padded to x8) ----
    mlp_layer<  8,  56,   5,  50, true >(W0, B0, wbuf, bbuf, act0, act1, tid);
    mlp_layer< 56, 104,  50, 100, true >(W1, B1, wbuf, bbuf, act1, act0, tid);
    mlp_layer<104, 104, 100, 100, true >(W2, B2, wbuf, bbuf, act0, act1, tid);
    mlp_layer<104, 104, 100, 100, true >(W3, B3, wbuf, bbuf, act1, act0, tid);
    mlp_layer<104,  56, 100,  50, true >(W4, B4, wbuf, bbuf, act0, act1, tid);
    mlp_layer< 56,  16,  50,  10, false>(W5, B5, wbuf, bbuf, act1, act0, tid);

    float g[10];
#pragma unroll
    for (int n = 0; n < 10; ++n) g[n] = act0[n * THREADS + tid];

    // ---- tensor bases, accumulated directly into raw ----
    float raw[9];
#pragma unroll
    for (int k = 0; k < 9; ++k) raw[k] = 0.f;

    // T1 = s
    axpy9(raw, g[0], s);

    float s2[9], w2[9];
    mm3(s, s, s2);
    mm3(w, w, w2);

    // T3 = s2 - tr(s2)/3 * I
    axpy9(raw, g[2], s2);
    {
        float c = g[2] * tr3(s2) * (1.f / 3.f);
        raw[0] -= c; raw[4] -= c; raw[8] -= c;
    }
    // T4 = w2 - tr(w2)/3 * I
    axpy9(raw, g[3], w2);
    {
        float c = g[3] * tr3(w2) * (1.f / 3.f);
        raw[0] -= c; raw[4] -= c; raw[8] -= c;
    }

    float sw[9], ws[9];
    mm3(s, w, sw);
    mm3(w, s, ws);
    // T2 = sw - ws
    axmy9(raw, g[1], sw, ws);

    float tA[9], tB[9];
    // T7 = ws*w2 - w2*sw
    mm3(ws, w2, tA);
    mm3(w2, sw, tB);
    axmy9(raw, g[6], tA, tB);
    // T8 = sw*s2 - s2*ws
    mm3(sw, s2, tA);
    mm3(s2, ws, tB);
    axmy9(raw, g[7], tA, tB);

    float ws2[9], s2w[9];
    mm3(w, s2, ws2);
    mm3(s2, w, s2w);
    // T5 = ws2 - s2w
    axmy9(raw, g[4], ws2, s2w);
    // T10 = ws2*w2 - w2*s2w
    mm3(ws2, w2, tA);
    mm3(w2, s2w, tB);
    axmy9(raw, g[9], tA, tB);

    // T6 = w2*s + s*w2 - (2/3) tr(s*w2) I
    mm3(w2, s, tA);
    mm3(s, w2, tB);
    axpy9(raw, g[5], tA);
    axpy9(raw, g[5], tB);
    {
        float c = g[5] * (2.f / 3.f) * tr3(tB);
        raw[0] -= c; raw[4] -= c; raw[8] -= c;
    }
    // T9 = w2*s2 + s2*w2 - (2/3) tr(s2*w2) I
    mm3(w2, s2, tA);
    mm3(s2, w2, tB);
    axpy9(raw, g[8], tA);
    axpy9(raw, g[8], tB);
    {
        float c = g[8] * (2.f / 3.f) * tr3(tB);
        raw[0] -= c; raw[4] -= c; raw[8] -= c;
    }

    // ---- deviator, symmetrize, normalize ----
    float Q[9];
#pragma unroll
    for (int k = 0; k < 9; ++k) Q[k] = raw[k];
    {
        float c = (raw[0] + raw[4] + raw[8]) * (1.f / 3.f);
        Q[0] -= c; Q[4] -= c; Q[8] -= c;
    }
    float Qs[9];
#pragma unroll
    for (int r = 0; r < 3; ++r)
#pragma unroll
        for (int c = 0; c < 3; ++c)
            Qs[r * 3 + c] = 0.5f * (Q[r * 3 + c] + Q[c * 3 + r]);

    float ns = 0.f;
#pragma unroll
    for (int k = 0; k < 9; ++k) ns += Qs[k] * Qs[k];
    float invn = 1.0f / sqrtf(ns + 1e-16f);

    if (b < Btot) {
        float* outQ = out + b * 9;
        float* outR = out + (size_t)Btot * 9 + b * 9;
#pragma unroll
        for (int k = 0; k < 9; ++k) {
            outQ[k] = Qs[k] * invn;
            outR[k] = raw[k];
        }
    }
}

extern "C" void kernel_launch(void* const* d_in, const int* in_sizes, int n_in,
                              void* d_out, int out_size)
{
    const float* s  = (const float*)d_in[0];
    const float* w  = (const float*)d_in[1];
    const float* W0 = (const float*)d_in[2];
    const float* B0 = (const float*)d_in[3];
    const float* W1 = (const float*)d_in[4];
    const float* B1 = (const float*)d_in[5];
    const float* W2 = (const float*)d_in[6];
    const float* B2 = (const float*)d_in[7];
    const float* W3 = (const float*)d_in[8];
    const float* B3 = (const float*)d_in[9];
    const float* W4 = (const float*)d_in[10];
    const float* B4 = (const float*)d_in[11];
    const float* W5 = (const float*)d_in[12];
    const float* B5 = (const float*)d_in[13];
    float* out = (float*)d_out;

    int Btot = in_sizes[0] / 9;
    int smem_bytes = SMEM_FLOATS * (int)sizeof(float);
    cudaFuncSetAttribute(tbnn_kernel, cudaFuncAttributeMaxDynamicSharedMemorySize, smem_bytes);

    int blocks = (Btot + THREADS - 1) / THREADS;
    tbnn_kernel<<<blocks, THREADS, smem_bytes>>>(
        s, w, W0, B0, W1, B1, W2, B2, W3, B3, W4, B4, W5, B5, out, Btot);
}

// round 2
// speedup vs baseline: 1.1969x; 1.1969x over previous
#include <cuda_runtime.h>
#include <math.h>

#define THREADS 160

// ---------------- 3x3 helpers ----------------
__device__ __forceinline__ void mm3(const float* a, const float* b, float* c) {
#pragma unroll
    for (int r = 0; r < 3; ++r)
#pragma unroll
        for (int k = 0; k < 3; ++k)
            c[r * 3 + k] = a[r * 3 + 0] * b[0 * 3 + k]
                         + a[r * 3 + 1] * b[1 * 3 + k]
                         + a[r * 3 + 2] * b[2 * 3 + k];
}
__device__ __forceinline__ float tr3(const float* a) { return a[0] + a[4] + a[8]; }
__device__ __forceinline__ float trAB(const float* a, const float* b) {
    float t = 0.f;
#pragma unroll
    for (int i = 0; i < 3; ++i)
#pragma unroll
        for (int k = 0; k < 3; ++k)
            t += a[i * 3 + k] * b[k * 3 + i];
    return t;
}
__device__ __forceinline__ void axpy9(float* acc, float g, const float* m) {
#pragma unroll
    for (int k = 0; k < 9; ++k) acc[k] += g * m[k];
}
__device__ __forceinline__ void axmy9(float* acc, float g, const float* m, const float* n) {
#pragma unroll
    for (int k = 0; k < 9; ++k) acc[k] += g * (m[k] - n[k]);
}

// -------------- weight staging: gmem -> smem, zero padded --------------
template <int KPAD, int NPAD, int KTRUE, int NTRUE>
__device__ __forceinline__ void stage(const float* __restrict__ Wg,
                                      const float* __restrict__ Bg,
                                      float* __restrict__ wbuf,
                                      float* __restrict__ bbuf, int tid)
{
    for (int idx = tid; idx < KPAD * NPAD; idx += THREADS) {
        int i = idx / NPAD;
        int j = idx - i * NPAD;
        wbuf[idx] = (i < KTRUE && j < NTRUE) ? __ldg(Wg + i * NTRUE + j) : 0.f;
    }
    for (int j = tid; j < NPAD; j += THREADS)
        bbuf[j] = (j < NTRUE) ? __ldg(Bg + j) : 0.f;
}

// -------------- GEMV layer: acc[NPAD] in registers, x streamed --------------
// entry sync: act stores + wbuf staging visible.  mid sync: all reads done
// before in-place act overwrite.
template <int KPAD, int NPAD, bool RELU>
__device__ __forceinline__ void gemv(const float* __restrict__ wbuf,
                                     const float* __restrict__ bbuf,
                                     float* __restrict__ act, int tid)
{
    __syncthreads();
    float acc[NPAD];
    const float4* bb4 = reinterpret_cast<const float4*>(bbuf);
#pragma unroll
    for (int j4 = 0; j4 < NPAD / 4; ++j4) {
        float4 b = bb4[j4];
        acc[4 * j4 + 0] = b.x; acc[4 * j4 + 1] = b.y;
        acc[4 * j4 + 2] = b.z; acc[4 * j4 + 3] = b.w;
    }
#pragma unroll 2
    for (int i = 0; i < KPAD; ++i) {
        float xi = act[i * THREADS + tid];
        const float4* wr = reinterpret_cast<const float4*>(wbuf + i * NPAD);
#pragma unroll
        for (int j4 = 0; j4 < NPAD / 4; ++j4) {
            float4 wv = wr[j4];
            acc[4 * j4 + 0] += xi * wv.x;
            acc[4 * j4 + 1] += xi * wv.y;
            acc[4 * j4 + 2] += xi * wv.z;
            acc[4 * j4 + 3] += xi * wv.w;
        }
    }
    __syncthreads();   // everyone done reading act + wbuf
#pragma unroll
    for (int j = 0; j < NPAD; ++j) {
        float a = acc[j];
        if (RELU) a = fmaxf(a, 0.1f * a);
        act[j * THREADS + tid] = a;
    }
}

// smem: wbuf 104*104, bbuf pad 112, act 104*THREADS
#define WBUF_FLOATS (104 * 104)
#define SMEM_FLOATS (WBUF_FLOATS + 112 + 104 * THREADS)

__global__ void __launch_bounds__(THREADS, 2) tbnn_kernel(
    const float* __restrict__ Sg, const float* __restrict__ Wg,
    const float* __restrict__ W0, const float* __restrict__ B0,
    const float* __restrict__ W1, const float* __restrict__ B1,
    const float* __restrict__ W2, const float* __restrict__ B2,
    const float* __restrict__ W3, const float* __restrict__ B3,
    const float* __restrict__ W4, const float* __restrict__ B4,
    const float* __restrict__ W5, const float* __restrict__ B5,
    float* __restrict__ out, int Btot)
{
    extern __shared__ float smem[];
    float* wbuf = smem;
    float* bbuf = wbuf + WBUF_FLOATS;
    float* act  = bbuf + 112;

    const int tid = threadIdx.x;
    const long b = (long)blockIdx.x * THREADS + tid;
    const long bb = (b < Btot) ? b : (long)Btot - 1;

    // ---- invariants (s,w regs are dead after this block) ----
    float inv[5];
    {
        float s[9], w[9];
#pragma unroll
        for (int k = 0; k < 9; ++k) {
            s[k] = Sg[bb * 9 + k];
            w[k] = Wg[bb * 9 + k];
        }
        float s2[9], w2[9];
        mm3(s, s, s2);
        mm3(w, w, w2);
        inv[0] = tr3(s2);
        inv[1] = tr3(w2);
        inv[2] = trAB(s2, s);
        inv[3] = trAB(w2, s);
        inv[4] = trAB(w2, s2);
    }

    // ---- layer 0: x in registers (K=5 true, N=56 padded) ----
    stage<5, 56, 5, 50>(W0, B0, wbuf, bbuf, tid);
    {
        __syncthreads();
        float acc[56];
        const float4* bb4 = reinterpret_cast<const float4*>(bbuf);
#pragma unroll
        for (int j4 = 0; j4 < 14; ++j4) {
            float4 v = bb4[j4];
            acc[4 * j4 + 0] = v.x; acc[4 * j4 + 1] = v.y;
            acc[4 * j4 + 2] = v.z; acc[4 * j4 + 3] = v.w;
        }
#pragma unroll
        for (int i = 0; i < 5; ++i) {
            float xi = inv[i];
            const float4* wr = reinterpret_cast<const float4*>(wbuf + i * 56);
#pragma unroll
            for (int j4 = 0; j4 < 14; ++j4) {
                float4 wv = wr[j4];
                acc[4 * j4 + 0] += xi * wv.x;
                acc[4 * j4 + 1] += xi * wv.y;
                acc[4 * j4 + 2] += xi * wv.z;
                acc[4 * j4 + 3] += xi * wv.w;
            }
        }
        __syncthreads();   // all warps done reading wbuf
#pragma unroll
        for (int j = 0; j < 56; ++j) {
            float a = acc[j];
            a = fmaxf(a, 0.1f * a);
            act[j * THREADS + tid] = a;
        }
    }

    // ---- layers 1..4 ----
    stage< 56, 104,  50, 100>(W1, B1, wbuf, bbuf, tid);
    gemv < 56, 104, true>(wbuf, bbuf, act, tid);
    stage<104, 104, 100, 100>(W2, B2, wbuf, bbuf, tid);
    gemv <104, 104, true>(wbuf, bbuf, act, tid);
    stage<104, 104, 100, 100>(W3, B3, wbuf, bbuf, tid);
    gemv <104, 104, true>(wbuf, bbuf, act, tid);
    stage<104,  56, 100,  50>(W4, B4, wbuf, bbuf, tid);
    gemv <104,  56, true>(wbuf, bbuf, act, tid);

    // ---- layer 5: K=56, N=16 padded, result stays in registers ----
    stage<56, 16, 50, 10>(W5, B5, wbuf, bbuf, tid);
    float g[10];
    {
        __syncthreads();
        float acc[16];
        const float4* bb4 = reinterpret_cast<const float4*>(bbuf);
#pragma unroll
        for (int j4 = 0; j4 < 4; ++j4) {
            float4 v = bb4[j4];
            acc[4 * j4 + 0] = v.x; acc[4 * j4 + 1] = v.y;
            acc[4 * j4 + 2] = v.z; acc[4 * j4 + 3] = v.w;
        }
#pragma unroll 2
        for (int i = 0; i < 56; ++i) {
            float xi = act[i * THREADS + tid];
            const float4* wr = reinterpret_cast<const float4*>(wbuf + i * 16);
#pragma unroll
            for (int j4 = 0; j4 < 4; ++j4) {
                float4 wv = wr[j4];
                acc[4 * j4 + 0] += xi * wv.x;
                acc[4 * j4 + 1] += xi * wv.y;
                acc[4 * j4 + 2] += xi * wv.z;
                acc[4 * j4 + 3] += xi * wv.w;
            }
        }
#pragma unroll
        for (int n = 0; n < 10; ++n) g[n] = acc[n];
    }

    // ---- reload s, w; build tensor bases directly into raw ----
    float s[9], w[9];
#pragma unroll
    for (int k = 0; k < 9; ++k) {
        s[k] = Sg[bb * 9 + k];
        w[k] = Wg[bb * 9 + k];
    }

    float raw[9];
#pragma unroll
    for (int k = 0; k < 9; ++k) raw[k] = 0.f;

    axpy9(raw, g[0], s);                       // T1

    float s2[9], w2[9];
    mm3(s, s, s2);
    mm3(w, w, w2);

    axpy9(raw, g[2], s2);                      // T3
    { float c = g[2] * tr3(s2) * (1.f / 3.f); raw[0] -= c; raw[4] -= c; raw[8] -= c; }
    axpy9(raw, g[3], w2);                      // T4
    { float c = g[3] * tr3(w2) * (1.f / 3.f); raw[0] -= c; raw[4] -= c; raw[8] -= c; }

    float sw[9], ws[9];
    mm3(s, w, sw);
    mm3(w, s, ws);
    axmy9(raw, g[1], sw, ws);                  // T2

    float tA[9], tB[9];
    mm3(ws, w2, tA);  mm3(w2, sw, tB);  axmy9(raw, g[6], tA, tB);  // T7
    mm3(sw, s2, tA);  mm3(s2, ws, tB);  axmy9(raw, g[7], tA, tB);  // T8

    float ws2[9], s2w[9];
    mm3(w, s2, ws2);
    mm3(s2, w, s2w);
    axmy9(raw, g[4], ws2, s2w);                // T5
    mm3(ws2, w2, tA); mm3(w2, s2w, tB); axmy9(raw, g[9], tA, tB);  // T10

    mm3(w2, s, tA);  mm3(s, w2, tB);           // T6
    axpy9(raw, g[5], tA); axpy9(raw, g[5], tB);
    { float c = g[5] * (2.f / 3.f) * tr3(tB); raw[0] -= c; raw[4] -= c; raw[8] -= c; }

    mm3(w2, s2, tA); mm3(s2, w2, tB);          // T9
    axpy9(raw, g[8], tA); axpy9(raw, g[8], tB);
    { float c = g[8] * (2.f / 3.f) * tr3(tB); raw[0] -= c; raw[4] -= c; raw[8] -= c; }

    // ---- deviator, symmetrize, normalize ----
    float Q[9];
#pragma unroll
    for (int k = 0; k < 9; ++k) Q[k] = raw[k];
    {
        float c = (raw[0] + raw[4] + raw[8]) * (1.f / 3.f);
        Q[0] -= c; Q[4] -= c; Q[8] -= c;
    }
    float Qs[9];
#pragma unroll
    for (int r = 0; r < 3; ++r)
#pragma unroll
        for (int c = 0; c < 3; ++c)
            Qs[r * 3 + c] = 0.5f * (Q[r * 3 + c] + Q[c * 3 + r]);

    float ns = 0.f;
#pragma unroll
    for (int k = 0; k < 9; ++k) ns += Qs[k] * Qs[k];
    float invn = 1.0f / sqrtf(ns + 1e-16f);

    if (b < Btot) {
        float* outQ = out + b * 9;
        float* outR = out + (size_t)Btot * 9 + b * 9;
#pragma unroll
        for (int k = 0; k < 9; ++k) {
            outQ[k] = Qs[k] * invn;
            outR[k] = raw[k];
        }
    }
}

extern "C" void kernel_launch(void* const* d_in, const int* in_sizes, int n_in,
                              void* d_out, int out_size)
{
    const float* s  = (const float*)d_in[0];
    const float* w  = (const float*)d_in[1];
    const float* W0 = (const float*)d_in[2];
    const float* B0 = (const float*)d_in[3];
    const float* W1 = (const float*)d_in[4];
    const float* B1 = (const float*)d_in[5];
    const float* W2 = (const float*)d_in[6];
    const float* B2 = (const float*)d_in[7];
    const float* W3 = (const float*)d_in[8];
    const float* B3 = (const float*)d_in[9];
    const float* W4 = (const float*)d_in[10];
    const float* B4 = (const float*)d_in[11];
    const float* W5 = (const float*)d_in[12];
    const float* B5 = (const float*)d_in[13];
    float* out = (float*)d_out;

    int Btot = in_sizes[0] / 9;
    int smem_bytes = SMEM_FLOATS * (int)sizeof(float);
    cudaFuncSetAttribute(tbnn_kernel, cudaFuncAttributeMaxDynamicSharedMemorySize, smem_bytes);

    int blocks = (Btot + THREADS - 1) / THREADS;
    tbnn_kernel<<<blocks, THREADS, smem_bytes>>>(
        s, w, W0, B0, W1, B1, W2, B2, W3, B3, W4, B4, W5, B5, out, Btot);
}